// round 15
// baseline (speedup 1.0000x reference)
#include <cuda_runtime.h>
#include <math.h>

// Problem dims
#define S_ 2048
#define B_ 64
#define I_ 256
#define H_ 512
#define ROWS_ (S_ * B_)          // 131072
#define BH_ (B_ * H_)

// ---------------- scratch (no cudaMalloc allowed) ----------------
__device__ float g_buf0[(size_t)S_ * BH_];   // xb0 -> y0 (in place)
__device__ float g_buf1[(size_t)S_ * BH_];   // y1
__device__ float g_zero[16 * H_];            // stays zero (bss)
// per-bgroup slot line: 16 CTA slots in one 128B line; MONOTONIC across launches
__device__ __align__(128) unsigned g_slots[8][32];

// ---------------- packed f32x2 FMA ----------------
__device__ __forceinline__ void fma2(float2& d, float ax, float ay,
                                     float bx, float by) {
    asm volatile(
        "{\n\t"
        ".reg .b64 ra, rb, rd;\n\t"
        "mov.b64 ra, {%2, %3};\n\t"
        "mov.b64 rb, {%4, %5};\n\t"
        "mov.b64 rd, {%0, %1};\n\t"
        "fma.rn.f32x2 rd, ra, rb, rd;\n\t"
        "mov.b64 {%0, %1}, rd;\n\t"
        "}"
        : "+f"(d.x), "+f"(d.y)
        : "f"(ax), "f"(ay), "f"(bx), "f"(by));
}
__device__ __forceinline__ void fma4(float2& acc, float4 a, float4 w) {
    fma2(acc, a.x, a.y, w.x, w.y);
    fma2(acc, a.z, a.w, w.z, w.w);
}

__device__ __forceinline__ unsigned su32(const void* p) {
    return (unsigned)__cvta_generic_to_shared(p);
}
__device__ __forceinline__ void cp16(unsigned dst, const void* src) {
    asm volatile("cp.async.cg.shared.global [%0], [%1], 16;" :: "r"(dst), "l"(src));
}
#define CP_COMMIT() asm volatile("cp.async.commit_group;" ::: "memory")
#define CP_WAIT0()  asm volatile("cp.async.wait_group 0;" ::: "memory")
#define CP_WAIT1()  asm volatile("cp.async.wait_group 1;" ::: "memory")

// ---------------- slot barrier ----------------
// wait: every warp polls the 16 slots (lanes 0..15, one 64B request) until all
// reach target (wrap-safe). No parked warps, no serialized RMWs.
__device__ __forceinline__ void slot_wait(const unsigned* slots, unsigned target) {
    const int lane = threadIdx.x & 31;
    const unsigned* p = slots + (lane & 15);
    unsigned f;
    do {
        asm volatile("ld.acquire.gpu.global.u32 %0, [%1];"
                     : "=r"(f) : "l"(p) : "memory");
    } while (!__all_sync(0xffffffffu, (int)(f - target) >= 0));
}

// ---------------- projection GEMM (layer 0 only) ----------------
#define TM 64
#define TN 64
#define KC 64
#define SAST 66

__global__ void __launch_bounds__(256) proj_kernel(
    const float* __restrict__ A,
    const float* __restrict__ W,
    const int*   __restrict__ Wmask,
    const float* __restrict__ bias1,
    const float* __restrict__ bias2,
    int K)
{
    __shared__ float SA[TM * SAST];
    __shared__ float SW[TN * SAST];

    float* C = g_buf0;
    const int m0 = blockIdx.x * TM;
    const int n0 = blockIdx.y * TN;
    const int tid = threadIdx.x;
    const int tx = tid & 15;
    const int ty = tid >> 4;

    float2 acc[4][4];
#pragma unroll
    for (int i = 0; i < 4; i++)
#pragma unroll
        for (int j = 0; j < 4; j++) acc[i][j] = make_float2(0.f, 0.f);

    for (int kc = 0; kc < K; kc += KC) {
#pragma unroll
        for (int t = tid; t < TM * 16; t += 256) {
            int r = t >> 4, q = t & 15;
            float4 v = *(const float4*)&A[(size_t)(m0 + r) * K + kc + 4 * q];
            int o = r * SAST + 4 * q;
            *(float2*)&SA[o]     = make_float2(v.x, v.y);
            *(float2*)&SA[o + 2] = make_float2(v.z, v.w);
        }
#pragma unroll
        for (int t = tid; t < TN * 16; t += 256) {
            int r = t >> 4, q = t & 15;
            size_t g = (size_t)(n0 + r) * K + kc + 4 * q;
            float4 v = *(const float4*)&W[g];
            int4  mm = *(const int4*)&Wmask[g];
            int o = r * SAST + 4 * q;
            SW[o]     = v.x * (float)mm.x;
            SW[o + 1] = v.y * (float)mm.y;
            SW[o + 2] = v.z * (float)mm.z;
            SW[o + 3] = v.w * (float)mm.w;
        }
        __syncthreads();

#pragma unroll 8
        for (int k = 0; k < KC; k += 2) {
            float2 a[4], w[4];
#pragma unroll
            for (int i = 0; i < 4; i++) a[i] = *(float2*)&SA[(ty + 16 * i) * SAST + k];
#pragma unroll
            for (int j = 0; j < 4; j++) w[j] = *(float2*)&SW[(tx + 16 * j) * SAST + k];
#pragma unroll
            for (int i = 0; i < 4; i++)
#pragma unroll
                for (int j = 0; j < 4; j++)
                    fma2(acc[i][j], a[i].x, a[i].y, w[j].x, w[j].y);
        }
        __syncthreads();
    }

#pragma unroll
    for (int j = 0; j < 4; j++) {
        int n = n0 + tx + 16 * j;
        float bb = bias1[n] + bias2[n];
#pragma unroll
        for (int i = 0; i < 4; i++) {
            int m = m0 + ty + 16 * i;
            C[(size_t)m * H_ + n] = acc[i][j].x + acc[i][j].y + bb;
        }
    }
}

// ---------------- fused 2-layer recurrence (R13 + slot barrier) -----------
// round t: L0 computes y0[t] (t<S), L1 computes y1[t-1] (t>=1).
// 128 CTAs = 8 bg x 16 hg; CTA = 8 rows x 32 cols; 256 threads:
// col = tid&31, ks = tid>>5 (8 x 64-k slices); weights (3x64 f32) in regs.
// Sync: per-bgroup 16-slot line; arrive = own-slot st.release; wait = all
// warps poll the line and vote.
#define NCTA 128
#define RTH  256
#define BROWS 8
#define HS0_OFF 0                    // [8][512]
#define HS1_OFF 4096                 // [8][512]
#define RED01_OFF 8192               // [8][256] float2
#define RED2_OFF 12288               // [8][256] float
#define SMEM_FLOATS 14336
#define RNN_SMEM_BYTES (SMEM_FLOATS * 4)   // 57344 B

__global__ void __launch_bounds__(RTH, 1) rnn_pipe_kernel(
    const float* __restrict__ Whh0, const int* __restrict__ m_hh0,
    const float* __restrict__ Wih1, const int* __restrict__ m_ih1,
    const float* __restrict__ Whh1, const int* __restrict__ m_hh1,
    const float* __restrict__ b_ih1, const float* __restrict__ b_hh1,
    float* __restrict__ out)
{
    extern __shared__ float smem[];
    float* hs0   = smem + HS0_OFF;
    float* hs1   = smem + HS1_OFF;
    float* red01 = smem + RED01_OFF;
    float* red2  = smem + RED2_OFF;

    const int bg = blockIdx.x >> 4;   // 0..7
    const int hg = blockIdx.x & 15;   // 0..15
    const int b0 = bg * BROWS;
    const int h0 = hg * 32;
    const int tid = threadIdx.x;
    const int col = tid & 31;         // output col within tile
    const int ks  = tid >> 5;         // 0..7, 64-k slice
    const int k0  = ks * 64;

    const unsigned* slots = g_slots[bg];
    unsigned* my_slot = &g_slots[bg][hg];

    // monotonic base: our own slot's value from the previous launch (all slots
    // share this value once a launch completes; slot is only written by us)
    unsigned base;
    asm volatile("ld.relaxed.gpu.global.u32 %0, [%1];" : "=r"(base) : "l"(my_slot));

    // ---- permanent register weights: 16 float4 per gemm (64 k) ----
    float4 wr0[16], wr1[16], wr2[16];
    {
        size_t ro = (size_t)(h0 + col) * H_ + k0;
#pragma unroll
        for (int q = 0; q < 16; q++) {
            float4 v; int4 mm;
            v = *(const float4*)&Whh0[ro + 4 * q];
            mm = *(const int4*)&m_hh0[ro + 4 * q];
            wr0[q] = make_float4(v.x * (float)mm.x, v.y * (float)mm.y,
                                 v.z * (float)mm.z, v.w * (float)mm.w);
            v = *(const float4*)&Wih1[ro + 4 * q];
            mm = *(const int4*)&m_ih1[ro + 4 * q];
            wr1[q] = make_float4(v.x * (float)mm.x, v.y * (float)mm.y,
                                 v.z * (float)mm.z, v.w * (float)mm.w);
            v = *(const float4*)&Whh1[ro + 4 * q];
            mm = *(const int4*)&m_hh1[ro + 4 * q];
            wr2[q] = make_float4(v.x * (float)mm.x, v.y * (float)mm.y,
                                 v.z * (float)mm.z, v.w * (float)mm.w);
        }
    }

    // output mapping: thread -> (row tid>>5, col tid&31)
    const int orow = tid >> 5;
    const int ocol = tid & 31;
    const size_t offO = (size_t)(b0 + orow) * H_ + (h0 + ocol);
    const float bL1 = __ldg(&b_ih1[h0 + ocol]) + __ldg(&b_hh1[h0 + ocol]);
    float xv = __ldg(&g_buf0[offO]);

    const unsigned hs0_b = su32(hs0);
    const unsigned hs1_b = su32(hs1);

    for (int t = 0; t <= S_; ++t) {
        float s0 = 0.f, s1 = 0.f, s2 = 0.f;

        if (t > 0) {
            // wait for round t-1 of this batch-group (all warps poll slots)
            slot_wait(slots, base + (unsigned)t);

            // stage hs0 = y0[t-1][b0..b0+8][0..512): 16KB contiguous
            {
                const float* src = g_buf0 + (size_t)(t - 1) * BH_ + (size_t)b0 * H_;
#pragma unroll
                for (int i = 0; i < 4; i++) {
                    int idx = tid + i * RTH;             // 0..1023 16B chunks
                    cp16(hs0_b + (unsigned)idx * 16u, src + (size_t)idx * 4);
                }
            }
            CP_COMMIT();
            // stage hs1 = y1[t-2] (zeros at t==1)
            {
                const float* src = (t >= 2)
                    ? g_buf1 + (size_t)(t - 2) * BH_ + (size_t)b0 * H_ : g_zero;
#pragma unroll
                for (int i = 0; i < 4; i++) {
                    int idx = tid + i * RTH;
                    cp16(hs1_b + (unsigned)idx * 16u, src + (size_t)idx * 4);
                }
            }
            CP_COMMIT();

            CP_WAIT1();              // hs0 ready
            __syncthreads();

            // gemm0 (Whh0) + gemm1 (Wih1) over hs0 rows; full-warp broadcast
#pragma unroll 2
            for (int r = 0; r < BROWS; r++) {
                const float* ap = &hs0[r * H_ + k0];
                float2 u0 = make_float2(0.f, 0.f);
                float2 u1 = make_float2(0.f, 0.f);
#pragma unroll
                for (int q = 0; q < 16; q++) {
                    float4 a = *(const float4*)&ap[4 * q];
                    fma4(u0, a, wr0[q]);
                    fma4(u1, a, wr1[q]);
                }
                *(float2*)&red01[(ks * 256 + r * 32 + col) * 2] =
                    make_float2(u0.x + u0.y, u1.x + u1.y);
            }

            CP_WAIT0();              // hs1 ready
            __syncthreads();

            // gemm2 (Whh1) over hs1 rows
#pragma unroll 2
            for (int r = 0; r < BROWS; r++) {
                const float* ap = &hs1[r * H_ + k0];
                float2 u2 = make_float2(0.f, 0.f);
#pragma unroll
                for (int q = 0; q < 16; q++) {
                    float4 a = *(const float4*)&ap[4 * q];
                    fma4(u2, a, wr2[q]);
                }
                red2[ks * 256 + r * 32 + col] = u2.x + u2.y;
            }
            __syncthreads();

            // 8-way k-slice reduction (1 output per thread)
#pragma unroll
            for (int k = 0; k < 8; k++) {
                float2 v = *(const float2*)&red01[(k * 256 + tid) * 2];
                s0 += v.x;
                s1 += v.y;
                s2 += red2[k * 256 + tid];
            }
        }

        if (t < S_) {
            float y0 = tanhf(s0 + xv);
            g_buf0[(size_t)t * BH_ + offO] = y0;
            if (t + 1 < S_)
                xv = __ldg(&g_buf0[(size_t)(t + 1) * BH_ + offO]);
        }
        if (t > 0) {
            float y1 = tanhf(s1 + s2 + bL1);
            if (t == S_) {
                out[offO] = y1;      // final y1[S-1] straight to output
            } else {
                g_buf1[(size_t)(t - 1) * BH_ + offO] = y1;
            }
        }

        // arrival: own-slot release store (no RMW chain, no extra hop).
        // skip at t==S: slot value S was stored at end of round S-1.
        if (t < S_) {
            __syncthreads();         // all y stores of this CTA issued
            if (tid == 0) {
                asm volatile("st.release.gpu.global.u32 [%0], %1;"
                             :: "l"(my_slot), "r"(base + (unsigned)(t + 1))
                             : "memory");
            }
        }
    }
}

// ---------------- launch ----------------
extern "C" void kernel_launch(void* const* d_in, const int* in_sizes, int n_in,
                              void* d_out, int out_size) {
    const float* x       = (const float*)d_in[0];
    const float* W_ih0   = (const float*)d_in[1];
    const float* W_hh0   = (const float*)d_in[2];
    const float* b_ih0   = (const float*)d_in[3];
    const float* b_hh0   = (const float*)d_in[4];
    const float* W_ih1   = (const float*)d_in[5];
    const float* W_hh1   = (const float*)d_in[6];
    const float* b_ih1   = (const float*)d_in[7];
    const float* b_hh1   = (const float*)d_in[8];
    const int*   m_ih0   = (const int*)d_in[9];
    const int*   m_hh0   = (const int*)d_in[10];
    const int*   m_ih1   = (const int*)d_in[11];
    const int*   m_hh1   = (const int*)d_in[12];
    float* out = (float*)d_out;

    static bool attr_set = false;
    if (!attr_set) {
        cudaFuncSetAttribute(rnn_pipe_kernel,
                             cudaFuncAttributeMaxDynamicSharedMemorySize,
                             RNN_SMEM_BYTES);
        attr_set = true;
    }

    // 2 launches/call => ncu -s 5 -c 1 lands on rnn_pipe_kernel
    dim3 pgrid(ROWS_ / TM, H_ / TN);
    proj_kernel<<<pgrid, 256>>>(x, W_ih0, m_ih0, b_ih0, b_hh0, I_);

    rnn_pipe_kernel<<<NCTA, RTH, RNN_SMEM_BYTES>>>(
        W_hh0, m_hh0, W_ih1, m_ih1, W_hh1, m_hh1, b_ih1, b_hh1, out);
}

// round 17
// speedup vs baseline: 1.5434x; 1.5434x over previous
#include <cuda_runtime.h>
#include <math.h>

// Problem dims
#define S_ 2048
#define B_ 64
#define I_ 256
#define H_ 512
#define ROWS_ (S_ * B_)          // 131072
#define BH_ (B_ * H_)

// ---------------- scratch (no cudaMalloc allowed) ----------------
__device__ float g_buf0[(size_t)S_ * BH_];   // xb0 -> y0 (in place)
__device__ float g_buf1[(size_t)S_ * BH_];   // y1
__device__ float g_zero[16 * H_];            // stays zero (bss)
__device__ unsigned g_ctr[256];              // per-bgroup arrival ctr  @ bg*32
__device__ unsigned g_flag[256];             // per-bgroup release flag @ bg*32
__device__ unsigned g_prog[S_];              // proj progress per step (+8/launch)
// ctr/flag/prog are MONOTONIC across launches; bases derived at kernel entry.
// flag advances exactly 2048 per launch -> launches = bf>>11, prog base = bf>>8.

// ---------------- packed f32x2 FMA ----------------
__device__ __forceinline__ void fma2(float2& d, float ax, float ay,
                                     float bx, float by) {
    asm volatile(
        "{\n\t"
        ".reg .b64 ra, rb, rd;\n\t"
        "mov.b64 ra, {%2, %3};\n\t"
        "mov.b64 rb, {%4, %5};\n\t"
        "mov.b64 rd, {%0, %1};\n\t"
        "fma.rn.f32x2 rd, ra, rb, rd;\n\t"
        "mov.b64 {%0, %1}, rd;\n\t"
        "}"
        : "+f"(d.x), "+f"(d.y)
        : "f"(ax), "f"(ay), "f"(bx), "f"(by));
}
__device__ __forceinline__ void fma4(float2& acc, float4 a, float4 w) {
    fma2(acc, a.x, a.y, w.x, w.y);
    fma2(acc, a.z, a.w, w.z, w.w);
}

__device__ __forceinline__ unsigned su32(const void* p) {
    return (unsigned)__cvta_generic_to_shared(p);
}
__device__ __forceinline__ void cp16(unsigned dst, const void* src) {
    asm volatile("cp.async.cg.shared.global [%0], [%1], 16;" :: "r"(dst), "l"(src));
}
#define CP_COMMIT() asm volatile("cp.async.commit_group;" ::: "memory")
#define CP_WAIT0()  asm volatile("cp.async.wait_group 0;" ::: "memory")
#define CP_WAIT1()  asm volatile("cp.async.wait_group 1;" ::: "memory")

// all-thread spin until *p - target >= 0 (wrap-safe)
__device__ __forceinline__ void spin_ge(const unsigned* p, unsigned target) {
    unsigned f;
    do {
        asm volatile("ld.acquire.gpu.global.u32 %0, [%1];"
                     : "=r"(f) : "l"(p) : "memory");
    } while ((int)(f - target) < 0);
}

// ---------------- geometry ----------------
#define NCTA 128                 // rnn blocks (8 bg x 16 hg)
#define RTH  256
#define GSZ  16
#define BROWS 8
#define TM 64
#define TN 64
#define KC 64
#define SAST 66
#define NPROJ (ROWS_ / TM * (H_ / TN))   // 2048*8 = 16384 proj blocks

// rnn dynamic smem layout (floats)
#define HS0_OFF 0                    // [8][512]
#define HS1_OFF 4096                 // [8][512]
#define RED01_OFF 8192               // [8][256] float2
#define RED2_OFF 12288               // [8][256] float
#define SMEM_FLOATS 14336
#define RNN_SMEM_BYTES (SMEM_FLOATS * 4)   // 57344 B

// ---------------- proj block body (layer-0 input projection tile) --------
__device__ __forceinline__ void proj_body(
    int pb,
    const float* __restrict__ A,
    const float* __restrict__ W,
    const int*   __restrict__ Wmask,
    const float* __restrict__ bias1,
    const float* __restrict__ bias2)
{
    __shared__ float SA[TM * SAST];
    __shared__ float SW[TN * SAST];

    const int K = I_;
    const int s  = pb >> 3;              // timestep (ascending with blockIdx)
    const int m0 = s * TM;
    const int n0 = (pb & 7) * TN;
    const int tid = threadIdx.x;
    const int tx = tid & 15;
    const int ty = tid >> 4;

    float2 acc[4][4];
#pragma unroll
    for (int i = 0; i < 4; i++)
#pragma unroll
        for (int j = 0; j < 4; j++) acc[i][j] = make_float2(0.f, 0.f);

    for (int kc = 0; kc < K; kc += KC) {
#pragma unroll
        for (int t = tid; t < TM * 16; t += 256) {
            int r = t >> 4, q = t & 15;
            float4 v = *(const float4*)&A[(size_t)(m0 + r) * K + kc + 4 * q];
            int o = r * SAST + 4 * q;
            *(float2*)&SA[o]     = make_float2(v.x, v.y);
            *(float2*)&SA[o + 2] = make_float2(v.z, v.w);
        }
#pragma unroll
        for (int t = tid; t < TN * 16; t += 256) {
            int r = t >> 4, q = t & 15;
            size_t g = (size_t)(n0 + r) * K + kc + 4 * q;
            float4 v = *(const float4*)&W[g];
            int4  mm = *(const int4*)&Wmask[g];
            int o = r * SAST + 4 * q;
            SW[o]     = v.x * (float)mm.x;
            SW[o + 1] = v.y * (float)mm.y;
            SW[o + 2] = v.z * (float)mm.z;
            SW[o + 3] = v.w * (float)mm.w;
        }
        __syncthreads();

#pragma unroll 8
        for (int k = 0; k < KC; k += 2) {
            float2 a[4], w[4];
#pragma unroll
            for (int i = 0; i < 4; i++) a[i] = *(float2*)&SA[(ty + 16 * i) * SAST + k];
#pragma unroll
            for (int j = 0; j < 4; j++) w[j] = *(float2*)&SW[(tx + 16 * j) * SAST + k];
#pragma unroll
            for (int i = 0; i < 4; i++)
#pragma unroll
                for (int j = 0; j < 4; j++)
                    fma2(acc[i][j], a[i].x, a[i].y, w[j].x, w[j].y);
        }
        __syncthreads();
    }

#pragma unroll
    for (int j = 0; j < 4; j++) {
        int n = n0 + tx + 16 * j;
        float bb = bias1[n] + bias2[n];
#pragma unroll
        for (int i = 0; i < 4; i++) {
            int m = m0 + ty + 16 * i;
            g_buf0[(size_t)m * H_ + n] = acc[i][j].x + acc[i][j].y + bb;
        }
    }

    // publish progress: 8 arrivals per timestep
    __syncthreads();
    if (tid == 0) {
        asm volatile("red.release.gpu.global.add.u32 [%0], %1;"
                     :: "l"(&g_prog[s]), "r"(1u) : "memory");
    }
}

// ---------------- rnn block body (R13 loop + prog gating) ----------------
__device__ __forceinline__ void rnn_body(
    const float* __restrict__ Whh0, const int* __restrict__ m_hh0,
    const float* __restrict__ Wih1, const int* __restrict__ m_ih1,
    const float* __restrict__ Whh1, const int* __restrict__ m_hh1,
    const float* __restrict__ b_ih1, const float* __restrict__ b_hh1,
    float* __restrict__ out)
{
    extern __shared__ float smem[];
    float* hs0   = smem + HS0_OFF;
    float* hs1   = smem + HS1_OFF;
    float* red01 = smem + RED01_OFF;
    float* red2  = smem + RED2_OFF;

    const int bg = blockIdx.x >> 4;   // 0..7
    const int hg = blockIdx.x & 15;   // 0..15
    const int b0 = bg * BROWS;
    const int h0 = hg * 32;
    const int tid = threadIdx.x;
    const int col = tid & 31;
    const int ks  = tid >> 5;         // 0..7, 64-k slice
    const int k0  = ks * 64;

    unsigned* ctr  = &g_ctr[bg * 32];
    unsigned* flag = &g_flag[bg * 32];

    // monotonic bases
    unsigned bc, bf;
    asm volatile("ld.relaxed.gpu.global.u32 %0, [%1];" : "=r"(bc) : "l"(ctr));
    asm volatile("ld.relaxed.gpu.global.u32 %0, [%1];" : "=r"(bf) : "l"(flag));
    const unsigned prog_target = (bf >> 8) + 8u;   // prog value when xb0[s] done

    // ---- permanent register weights: 16 float4 per gemm (64 k) ----
    float4 wr0[16], wr1[16], wr2[16];
    {
        size_t ro = (size_t)(h0 + col) * H_ + k0;
#pragma unroll
        for (int q = 0; q < 16; q++) {
            float4 v; int4 mm;
            v = *(const float4*)&Whh0[ro + 4 * q];
            mm = *(const int4*)&m_hh0[ro + 4 * q];
            wr0[q] = make_float4(v.x * (float)mm.x, v.y * (float)mm.y,
                                 v.z * (float)mm.z, v.w * (float)mm.w);
            v = *(const float4*)&Wih1[ro + 4 * q];
            mm = *(const int4*)&m_ih1[ro + 4 * q];
            wr1[q] = make_float4(v.x * (float)mm.x, v.y * (float)mm.y,
                                 v.z * (float)mm.z, v.w * (float)mm.w);
            v = *(const float4*)&Whh1[ro + 4 * q];
            mm = *(const int4*)&m_hh1[ro + 4 * q];
            wr2[q] = make_float4(v.x * (float)mm.x, v.y * (float)mm.y,
                                 v.z * (float)mm.z, v.w * (float)mm.w);
        }
    }

    const int orow = tid >> 5;
    const int ocol = tid & 31;
    const size_t offO = (size_t)(b0 + orow) * H_ + (h0 + ocol);
    const float bL1 = __ldg(&b_ih1[h0 + ocol]) + __ldg(&b_hh1[h0 + ocol]);

    // xv = xb0[0], gated on proj progress for step 0
    spin_ge(&g_prog[0], prog_target);
    float xv = __ldg(&g_buf0[offO]);

    const unsigned hs0_b = su32(hs0);
    const unsigned hs1_b = su32(hs1);

    for (int t = 0; t <= S_; ++t) {
        float s0 = 0.f, s1 = 0.f, s2 = 0.f;

        if (t > 0) {
            spin_ge(flag, bf + (unsigned)t);

            {   // stage hs0 = y0[t-1]
                const float* src = g_buf0 + (size_t)(t - 1) * BH_ + (size_t)b0 * H_;
#pragma unroll
                for (int i = 0; i < 4; i++) {
                    int idx = tid + i * RTH;
                    cp16(hs0_b + (unsigned)idx * 16u, src + (size_t)idx * 4);
                }
            }
            CP_COMMIT();
            {   // stage hs1 = y1[t-2] (zeros at t==1)
                const float* src = (t >= 2)
                    ? g_buf1 + (size_t)(t - 2) * BH_ + (size_t)b0 * H_ : g_zero;
#pragma unroll
                for (int i = 0; i < 4; i++) {
                    int idx = tid + i * RTH;
                    cp16(hs1_b + (unsigned)idx * 16u, src + (size_t)idx * 4);
                }
            }
            CP_COMMIT();

            CP_WAIT1();
            __syncthreads();

#pragma unroll 2
            for (int r = 0; r < BROWS; r++) {
                const float* ap = &hs0[r * H_ + k0];
                float2 u0 = make_float2(0.f, 0.f);
                float2 u1 = make_float2(0.f, 0.f);
#pragma unroll
                for (int q = 0; q < 16; q++) {
                    float4 a = *(const float4*)&ap[4 * q];
                    fma4(u0, a, wr0[q]);
                    fma4(u1, a, wr1[q]);
                }
                *(float2*)&red01[(ks * 256 + r * 32 + col) * 2] =
                    make_float2(u0.x + u0.y, u1.x + u1.y);
            }

            CP_WAIT0();
            __syncthreads();

#pragma unroll 2
            for (int r = 0; r < BROWS; r++) {
                const float* ap = &hs1[r * H_ + k0];
                float2 u2 = make_float2(0.f, 0.f);
#pragma unroll
                for (int q = 0; q < 16; q++) {
                    float4 a = *(const float4*)&ap[4 * q];
                    fma4(u2, a, wr2[q]);
                }
                red2[ks * 256 + r * 32 + col] = u2.x + u2.y;
            }
            __syncthreads();

#pragma unroll
            for (int k = 0; k < 8; k++) {
                float2 v = *(const float2*)&red01[(k * 256 + tid) * 2];
                s0 += v.x;
                s1 += v.y;
                s2 += red2[k * 256 + tid];
            }
        }

        if (t < S_) {
            float y0 = tanhf(s0 + xv);
            g_buf0[(size_t)t * BH_ + offO] = y0;
            if (t + 1 < S_) {
                spin_ge(&g_prog[t + 1], prog_target);   // proj ahead? (cheap)
                xv = __ldg(&g_buf0[(size_t)(t + 1) * BH_ + offO]);
            }
        }
        if (t > 0) {
            float y1 = tanhf(s1 + s2 + bL1);
            if (t == S_) {
                out[offO] = y1;
            } else {
                g_buf1[(size_t)(t - 1) * BH_ + offO] = y1;
            }
        }

        if (t < S_) {
            __syncthreads();
            if (tid == 0) {
                unsigned old;
                asm volatile("atom.acq_rel.gpu.global.add.u32 %0, [%1], 1;"
                             : "=r"(old) : "l"(ctr) : "memory");
                if (old == bc + (unsigned)((t + 1) * GSZ - 1)) {
                    asm volatile("st.release.gpu.global.u32 [%0], %1;"
                                 :: "l"(flag), "r"(bf + (unsigned)(t + 1))
                                 : "memory");
                }
            }
        }
    }
}

// ---------------- fused mega-kernel --------------------------------------
// blocks [0, NCTA): persistent rnn (all resident in wave 1).
// blocks [NCTA, NCTA+NPROJ): proj tiles, ascending timestep order, streaming
// through the SMs the rnn doesn't occupy. proj never waits on rnn.
__global__ void __launch_bounds__(RTH, 1) mega_kernel(
    const float* __restrict__ x,
    const float* __restrict__ Wih0, const int* __restrict__ m_ih0,
    const float* __restrict__ b_ih0, const float* __restrict__ b_hh0,
    const float* __restrict__ Whh0, const int* __restrict__ m_hh0,
    const float* __restrict__ Wih1, const int* __restrict__ m_ih1,
    const float* __restrict__ Whh1, const int* __restrict__ m_hh1,
    const float* __restrict__ b_ih1, const float* __restrict__ b_hh1,
    float* __restrict__ out)
{
    if (blockIdx.x < NCTA) {
        rnn_body(Whh0, m_hh0, Wih1, m_ih1, Whh1, m_hh1, b_ih1, b_hh1, out);
    } else {
        proj_body((int)blockIdx.x - NCTA, x, Wih0, m_ih0, b_ih0, b_hh0);
    }
}

// ---------------- launch ----------------
extern "C" void kernel_launch(void* const* d_in, const int* in_sizes, int n_in,
                              void* d_out, int out_size) {
    const float* x       = (const float*)d_in[0];
    const float* W_ih0   = (const float*)d_in[1];
    const float* W_hh0   = (const float*)d_in[2];
    const float* b_ih0   = (const float*)d_in[3];
    const float* b_hh0   = (const float*)d_in[4];
    const float* W_ih1   = (const float*)d_in[5];
    const float* W_hh1   = (const float*)d_in[6];
    const float* b_ih1   = (const float*)d_in[7];
    const float* b_hh1   = (const float*)d_in[8];
    const int*   m_ih0   = (const int*)d_in[9];
    const int*   m_hh0   = (const int*)d_in[10];
    const int*   m_ih1   = (const int*)d_in[11];
    const int*   m_hh1   = (const int*)d_in[12];
    float* out = (float*)d_out;

    static bool attr_set = false;
    if (!attr_set) {
        cudaFuncSetAttribute(mega_kernel,
                             cudaFuncAttributeMaxDynamicSharedMemorySize,
                             RNN_SMEM_BYTES);
        attr_set = true;
    }

    mega_kernel<<<NCTA + NPROJ, RTH, RNN_SMEM_BYTES>>>(
        x, W_ih0, m_ih0, b_ih0, b_hh0,
        W_hh0, m_hh0, W_ih1, m_ih1, W_hh1, m_hh1, b_ih1, b_hh1, out);
}